// round 9
// baseline (speedup 1.0000x reference)
#include <cuda_runtime.h>
#include <math.h>

#define N_NODES   8192
#define K_NBR     64
#define TWO_N     (2 * N_NODES)
#define BN_EPS    1e-3f

// Fused kernel: 64 builder blocks + 512 GEMV blocks = 576 blocks, all
// co-resident (<= 148 SMs * 4 blocks at 256 threads), so the flag spin
// can never deadlock.
#define N_BUILDERS     64
#define NODES_PER_B    (N_NODES / N_BUILDERS)   // 128
#define COL_TILES      8
#define ROW_CHUNKS     64
#define ROWS_PER_CHUNK 256
#define THREADS_B      256
#define GRID_TOTAL     (N_BUILDERS + COL_TILES * ROW_CHUNKS)

// scratch (no allocation allowed in kernel_launch). Zero-initialized at load;
// flags/counters are self-resetting each execution -> graph-replay safe.
__device__ float g_h[TWO_N];                     // only rows >= N used
__device__ float g_part[ROW_CHUNKS * N_NODES];
__device__ int   g_flag[N_BUILDERS];
__device__ int   g_cnt[N_BUILDERS];

// ---------------------------------------------------------------------------
// Fused builder + split-K GEMV (unchanged from R8 — measured win).
// ---------------------------------------------------------------------------
__global__ __launch_bounds__(THREADS_B)
void fused_kernel(const float* __restrict__ x,
                  const int* __restrict__ adj,
                  const float* __restrict__ W,
                  const float* __restrict__ gamma,
                  const float* __restrict__ beta,
                  const float* __restrict__ mean,
                  const float* __restrict__ var)
{
    __shared__ float sh[ROWS_PER_CHUNK];
    const int tid = threadIdx.x;

    if (blockIdx.x < N_BUILDERS) {
        // ================= builder: BN(x + ngh_sum) for 128 nodes ==========
        const int b        = blockIdx.x;
        const int warpId   = tid >> 5;
        const int lane     = tid & 31;
        const int nodeBase = b * NODES_PER_B + warpId * 16;   // 16 nodes/warp
        const int2* adj2   = reinterpret_cast<const int2*>(adj);

        #pragma unroll
        for (int g = 0; g < 16; g += 8) {
            int2 a[8];
            #pragma unroll
            for (int i = 0; i < 8; ++i)
                a[i] = __ldg(&adj2[(nodeBase + g + i) * 32 + lane]);

            float s[8];
            #pragma unroll
            for (int i = 0; i < 8; ++i)
                s[i] = __ldg(&x[a[i].x]) + __ldg(&x[a[i].y]);

            #pragma unroll
            for (int off = 16; off > 0; off >>= 1) {
                #pragma unroll
                for (int i = 0; i < 8; ++i)
                    s[i] += __shfl_down_sync(0xffffffffu, s[i], off);
            }

            if (lane == 0) {
                #pragma unroll
                for (int i = 0; i < 8; ++i) {
                    const int node = nodeBase + g + i;
                    const int j    = N_NODES + node;
                    float agg = __ldg(&x[node]) + s[i];
                    float inv = rsqrtf(var[j] + BN_EPS);
                    g_h[j] = (agg - mean[j]) * inv * gamma[j] + beta[j];
                }
            }
        }

        __threadfence();     // make this thread's h writes GPU-visible
        __syncthreads();     // all threads' writes done + fenced
        if (tid == 0)
            atomicExch(&g_flag[b], 1);   // release
        return;
    }

    // ================= GEMV block ==========================================
    const int gid     = blockIdx.x - N_BUILDERS;
    const int colTile = gid & (COL_TILES - 1);
    const int chunk   = gid >> 3;                 // 0..63
    const int colBase = colTile * (THREADS_B * 4) + tid * 4;
    const int rowBase = chunk * ROWS_PER_CHUNK;
    const int row     = rowBase + tid;

    if (chunk < ROW_CHUNKS / 2) {
        // lower half: h = BN(x[row]) computed inline -> no wait, stream now
        float v   = x[row];
        float inv = rsqrtf(var[row] + BN_EPS);
        sh[tid] = (v - mean[row]) * inv * gamma[row] + beta[row];
        __syncthreads();
    } else {
        // upper half: wait for the two builders covering rows [rowBase, +256)
        const int f0 = 2 * (chunk - ROW_CHUNKS / 2);
        if (tid == 0) {
            while (atomicAdd(&g_flag[f0], 0) == 0)     __nanosleep(64);
            while (atomicAdd(&g_flag[f0 + 1], 0) == 0) __nanosleep(64);
            __threadfence();   // acquire
        }
        __syncthreads();
        sh[tid] = __ldcg(&g_h[row]);   // L2 read, builders already applied BN
        __syncthreads();
        // self-resetting consumption (8 consumer blocks per flag)
        if (tid == 0) {
            if (atomicAdd(&g_cnt[f0], 1) == COL_TILES - 1) {
                atomicExch(&g_cnt[f0], 0);
                atomicExch(&g_flag[f0], 0);
            }
            if (atomicAdd(&g_cnt[f0 + 1], 1) == COL_TILES - 1) {
                atomicExch(&g_cnt[f0 + 1], 0);
                atomicExch(&g_flag[f0 + 1], 0);
            }
        }
    }

    // ---- stream W: proven inner loop (coalesced float4, unroll 8) --------
    float4 acc = make_float4(0.f, 0.f, 0.f, 0.f);
    const float* wp = W + (long long)rowBase * N_NODES + colBase;

    #pragma unroll 8
    for (int r = 0; r < ROWS_PER_CHUNK; ++r) {
        float  hv = sh[r];
        float4 w  = *reinterpret_cast<const float4*>(wp);
        acc.x = fmaf(hv, w.x, acc.x);
        acc.y = fmaf(hv, w.y, acc.y);
        acc.z = fmaf(hv, w.z, acc.z);
        acc.w = fmaf(hv, w.w, acc.w);
        wp += N_NODES;
    }

    *reinterpret_cast<float4*>(&g_part[chunk * N_NODES + colBase]) = acc;
}

// ---------------------------------------------------------------------------
// K3: high-parallelism reduce. grid 128 x 512 threads.
// Block owns 64 columns; 8 chunk-groups of 8 chunks each. Loads are
// coalesced over jLocal (64 x 4B = 256B segments), MLP=8 per thread,
// 64K threads total. smem[8][64] combine, 64 threads finish gelu.
// ---------------------------------------------------------------------------
__global__ __launch_bounds__(512)
void reduce_gelu_kernel(const float* __restrict__ bias,
                        float* __restrict__ out)
{
    __shared__ float red[8][64];

    const int jLocal = threadIdx.x & 63;
    const int cg     = threadIdx.x >> 6;          // 0..7
    const int j      = blockIdx.x * 64 + jLocal;

    float s = 0.f;
    #pragma unroll
    for (int i = 0; i < ROW_CHUNKS / 8; ++i) {    // 8 chunks per thread
        int c = cg * (ROW_CHUNKS / 8) + i;
        s += g_part[c * N_NODES + j];
    }
    red[cg][jLocal] = s;
    __syncthreads();

    if (threadIdx.x < 64) {
        float t = 0.f;
        #pragma unroll
        for (int k = 0; k < 8; ++k)
            t += red[k][jLocal];
        float z = t + bias[j];
        out[j] = 0.5f * z * (1.0f + erff(z * 0.70710678118654752440f));
    }
}

// ---------------------------------------------------------------------------
extern "C" void kernel_launch(void* const* d_in, const int* in_sizes, int n_in,
                              void* d_out, int out_size)
{
    const float* x     = (const float*)d_in[0];  // input_data [1,N]
    const int*   adj   = (const int*)d_in[1];    // adj [N,K] int32 (JAX x64 off)
    // d_in[2] = edge_weights (unused by reference)
    const float* W     = (const float*)d_in[3];  // [2N, N]
    const float* b     = (const float*)d_in[4];  // [N]
    const float* gamma = (const float*)d_in[5];  // [2N]
    const float* beta  = (const float*)d_in[6];  // [2N]
    const float* mean  = (const float*)d_in[7];  // [2N]
    const float* var   = (const float*)d_in[8];  // [2N]
    float*       out   = (float*)d_out;

    fused_kernel<<<GRID_TOTAL, THREADS_B>>>(x, adj, W, gamma, beta, mean, var);

    reduce_gelu_kernel<<<N_NODES / 64, 512>>>(b, out);
}